// round 1
// baseline (speedup 1.0000x reference)
#include <cuda_runtime.h>
#include <cuda_bf16.h>

// Problem: B=32768 rows, N=64. loss = (1/B) * sum_b sum_{i<j} max(0, (s_i - s_j) + 0.1*(j-i))
// where s = scores gathered by stable argsort(labels).
// Key identity: with t_k = s_sorted[k] - 0.1*k, pair term = relu(t_i - t_j).

#define BATCH 32768
#define NROW  64
#define WARPS_PER_BLOCK 8
#define GRID1 (BATCH / WARPS_PER_BLOCK)   // 4096 blocks, one row per warp

__device__ float g_partials[GRID1];

__device__ __forceinline__ float warp_sum(float v) {
#pragma unroll
    for (int o = 16; o; o >>= 1) v += __shfl_xor_sync(0xffffffffu, v, o);
    return v;
}

__global__ __launch_bounds__(WARPS_PER_BLOCK * 32)
void pair_loss_kernel(const float* __restrict__ scores,
                      const float* __restrict__ labels) {
    __shared__ float sh[WARPS_PER_BLOCK][NROW];
    __shared__ float wpart[WARPS_PER_BLOCK];

    const int warp = threadIdx.x >> 5;
    const int lane = threadIdx.x & 31;
    const int row  = blockIdx.x * WARPS_PER_BLOCK + warp;  // < BATCH by construction

    float acc = 0.f;
    {
        // Coalesced vector loads: each lane owns original elements k0=2*lane, k0+1.
        const float2 l = reinterpret_cast<const float2*>(labels + (size_t)row * NROW)[lane];
        const float2 s = reinterpret_cast<const float2*>(scores + (size_t)row * NROW)[lane];
        const int k0 = 2 * lane;
        const int k1 = 2 * lane + 1;

        sh[warp][k0] = l.x;
        sh[warp][k1] = l.y;
        __syncwarp();

        // Stable rank: rank_k = #{m: lab_m < lab_k} + #{m < k: lab_m == lab_k}
        int r0 = 0, r1 = 0;
#pragma unroll
        for (int m = 0; m < NROW; ++m) {
            const float v = sh[warp][m];
            r0 += (int)((v < l.x) | ((v == l.x) & (m < k0)));
            r1 += (int)((v < l.y) | ((v == l.y) & (m < k1)));
        }
        __syncwarp();

        // Scatter t[rank] = score - 0.1*rank (ranks are a permutation -> no conflicts).
        sh[warp][r0] = fmaf(-0.1f, (float)r0, s.x);
        sh[warp][r1] = fmaf(-0.1f, (float)r1, s.y);
        __syncwarp();

        const float t0 = sh[warp][lane];        // sorted position i = lane
        const float t1 = sh[warp][lane + 32];   // sorted position i = lane + 32

        // sum_{i<j} relu(t_i - t_j); lane covers i=lane and i=lane+32.
#pragma unroll
        for (int j = 1; j < NROW; ++j) {
            const float tj = sh[warp][j];
            if (lane < j)      acc += fmaxf(t0 - tj, 0.f);
            if (lane + 32 < j) acc += fmaxf(t1 - tj, 0.f);  // compile-time dead for j<=32
        }
    }

    // Deterministic block reduction (fixed tree order, no float atomics).
    const float wsum = warp_sum(acc);
    if (lane == 0) wpart[warp] = wsum;
    __syncthreads();
    if (warp == 0) {
        float v = (lane < WARPS_PER_BLOCK) ? wpart[lane] : 0.f;
        v = warp_sum(v);
        if (lane == 0) g_partials[blockIdx.x] = v;
    }
}

__global__ __launch_bounds__(256)
void reduce_kernel(float* __restrict__ out) {
    __shared__ float sp[8];
    const int t = threadIdx.x;
    float v = 0.f;
#pragma unroll
    for (int i = 0; i < GRID1 / 256; ++i) v += g_partials[t + i * 256];
    v = warp_sum(v);
    const int warp = t >> 5, lane = t & 31;
    if (lane == 0) sp[warp] = v;
    __syncthreads();
    if (warp == 0) {
        float x = (lane < 8) ? sp[lane] : 0.f;
        x = warp_sum(x);
        if (lane == 0) out[0] = x * (1.0f / (float)BATCH);
    }
}

extern "C" void kernel_launch(void* const* d_in, const int* in_sizes, int n_in,
                              void* d_out, int out_size) {
    const float* scores = (const float*)d_in[0];
    const float* labels = (const float*)d_in[1];
    float* out = (float*)d_out;

    pair_loss_kernel<<<GRID1, WARPS_PER_BLOCK * 32>>>(scores, labels);
    reduce_kernel<<<1, 256>>>(out);
}

// round 2
// speedup vs baseline: 1.2879x; 1.2879x over previous
#include <cuda_runtime.h>
#include <cuda_bf16.h>

// loss = (1/B) * sum_b sum_{i<j} max(0, (s_i - s_j) + 0.1*(j-i)),  s = scores[argsort(labels)]
// With t_k = s_sorted_k - 0.1k:  pair term = relu(t_i - t_j), and
//   sum_{i<j} relu(t_i-t_j) = 0.5*sum_k t_k*(63-2k)  +  0.5*sum_m v_m*(2m-63),  v = sort(t) ascending.
// So: warp bitonic sort (label,score) -> t -> linear weighted sum -> keys-only bitonic sort of t
//     -> second weighted sum. No O(N^2) loops.

#define BATCH 32768
#define NROW  64
#define THREADS 256
#define WARPS 8
#define ROWS_PER_WARP 4
#define GRID (BATCH / (WARPS * ROWS_PER_WARP))   // 1024

__device__ float g_partials[GRID];
__device__ unsigned int g_done = 0;

__device__ __forceinline__ float warp_sum(float v) {
#pragma unroll
    for (int o = 16; o; o >>= 1) v += __shfl_xor_sync(0xffffffffu, v, o);
    return v;
}

__global__ __launch_bounds__(THREADS)
void loss_kernel(const float* __restrict__ scores,
                 const float* __restrict__ labels,
                 float* __restrict__ out) {
    __shared__ float wpart[WARPS];
    __shared__ bool  isLast;

    const int warp = threadIdx.x >> 5;
    const int lane = threadIdx.x & 31;
    const int wg   = blockIdx.x * WARPS + warp;

    // Element idx = 2*lane + slot. Position-weight coefficients (63 - 2*idx):
    const float c0 = 63.0f - 4.0f * (float)lane;   // slot 0
    const float c1 = c0 - 2.0f;                    // slot 1

    float acc = 0.f;

#pragma unroll 1
    for (int r = 0; r < ROWS_PER_WARP; ++r) {
        const int row = wg * ROWS_PER_WARP + r;
        const float2 L = reinterpret_cast<const float2*>(labels)[row * 32 + lane];
        const float2 S = reinterpret_cast<const float2*>(scores)[row * 32 + lane];
        float k0 = L.x, k1 = L.y;   // keys (labels), slots 0/1
        float v0 = S.x, v1 = S.y;   // payloads (scores)

        // ---- Bitonic sort 64 elems by label, carrying score. idx = 2*lane + slot ----
#pragma unroll
        for (int k = 2; k <= 64; k <<= 1) {
            const bool up = (lane & (k >> 1)) == 0;   // (idx & k) == 0
#pragma unroll
            for (int d = k >> 1; d >= 2; d >>= 1) {   // inter-lane steps
                const bool wantMin = (((lane & (d >> 1)) == 0) == up);
                const float pk0 = __shfl_xor_sync(0xffffffffu, k0, d >> 1);
                const float pv0 = __shfl_xor_sync(0xffffffffu, v0, d >> 1);
                const float pk1 = __shfl_xor_sync(0xffffffffu, k1, d >> 1);
                const float pv1 = __shfl_xor_sync(0xffffffffu, v1, d >> 1);
                const bool s0 = wantMin ? (pk0 < k0) : (pk0 > k0);
                const bool s1 = wantMin ? (pk1 < k1) : (pk1 > k1);
                if (s0) { k0 = pk0; v0 = pv0; }
                if (s1) { k1 = pk1; v1 = pv1; }
            }
            { // d == 1: intra-lane compare-exchange between slots
                const bool sw = up ? (k0 > k1) : (k0 < k1);
                if (sw) { float tk = k0; k0 = k1; k1 = tk;
                          float tv = v0; v0 = v1; v1 = tv; }
            }
        }

        // ---- t_p = s_sorted_p - 0.1*p at p = 2*lane, 2*lane+1 ----
        float t0 = fmaf(-0.2f, (float)lane, v0);
        float t1 = fmaf(-0.2f, (float)lane, v1) - 0.1f;

        // linear term: sum_k t_k * (63 - 2k)
        acc += t0 * c0 + t1 * c1;

        // ---- keys-only bitonic sort of t (ascending) ----
#pragma unroll
        for (int k = 2; k <= 64; k <<= 1) {
            const bool up = (lane & (k >> 1)) == 0;
#pragma unroll
            for (int d = k >> 1; d >= 2; d >>= 1) {
                const bool wantMin = (((lane & (d >> 1)) == 0) == up);
                const float p0 = __shfl_xor_sync(0xffffffffu, t0, d >> 1);
                const float p1 = __shfl_xor_sync(0xffffffffu, t1, d >> 1);
                t0 = wantMin ? fminf(t0, p0) : fmaxf(t0, p0);
                t1 = wantMin ? fminf(t1, p1) : fmaxf(t1, p1);
            }
            {
                const float lo = fminf(t0, t1), hi = fmaxf(t0, t1);
                t0 = up ? lo : hi;
                t1 = up ? hi : lo;
            }
        }

        // abs term: sum_m v_m * (2m - 63) = -(v0*c0 + v1*c1)
        acc -= t0 * c0 + t1 * c1;
    }

    // ---- deterministic block reduction ----
    const float ws = warp_sum(acc);
    if (lane == 0) wpart[warp] = ws;
    __syncthreads();
    if (warp == 0) {
        float v = (lane < WARPS) ? wpart[lane] : 0.f;
        v = warp_sum(v);
        if (lane == 0) {
            g_partials[blockIdx.x] = v;
            __threadfence();
            const unsigned t = atomicAdd(&g_done, 1u);
            isLast = (t == GRID - 1);
        }
    }
    __syncthreads();

    // ---- last block: fixed-order final reduction (deterministic), reset counter ----
    if (isLast) {
        float v = 0.f;
#pragma unroll
        for (int i = 0; i < GRID / THREADS; ++i)
            v += __ldcg(&g_partials[threadIdx.x + i * THREADS]);
        v = warp_sum(v);
        if (lane == 0) wpart[warp] = v;
        __syncthreads();
        if (warp == 0) {
            float x = (lane < WARPS) ? wpart[lane] : 0.f;
            x = warp_sum(x);
            if (lane == 0) {
                out[0] = x * (0.5f / (float)BATCH);  // fold the 1/2 from relu identity + 1/B mean
                g_done = 0;                           // reset for next graph replay
            }
        }
    }
}

extern "C" void kernel_launch(void* const* d_in, const int* in_sizes, int n_in,
                              void* d_out, int out_size) {
    const float* scores = (const float*)d_in[0];
    const float* labels = (const float*)d_in[1];
    float* out = (float*)d_out;
    loss_kernel<<<GRID, THREADS>>>(scores, labels, out);
}

// round 3
// speedup vs baseline: 1.7266x; 1.3406x over previous
#include <cuda_runtime.h>
#include <cuda_bf16.h>

// loss = (1/B) * sum_b sum_{i<j} max(0, (s_i - s_j) + 0.1*(j-i)),  s = scores[argsort(labels)]
// t_k = s_sorted_k - 0.1k  ->  pair term = relu(t_i - t_j), and
//   sum_{i<j} relu(t_i-t_j) = 0.5*[ sum_k t_k*(63-2k) + sum_m v_m*(2m-63) ],  v = sort(t) asc.
// Sort #1: labels as order-preserving uint32 with embedded 6-bit index (keys-only, IMNMX),
//          then gather scores via 2-SHFL. Sort #2: keys-only float sort of t (FMNMX).
// Two rows interleaved per warp for ILP on the SHFL dependency chain.

#define BATCH 32768
#define THREADS 256
#define WARPS 8
#define RPW 2
#define GRID (BATCH / (WARPS * RPW))   // 2048

__device__ float g_partials[GRID];
__device__ unsigned int g_done = 0;

__device__ __forceinline__ float warp_sum(float v) {
#pragma unroll
    for (int o = 16; o; o >>= 1) v += __shfl_xor_sync(0xffffffffu, v, o);
    return v;
}

// order-preserving float -> uint32 (ascending), low 6 bits cleared for index
__device__ __forceinline__ unsigned int pack_key(float f, int idx) {
    unsigned int u = __float_as_uint(f);
    u ^= (unsigned int)((int)u >> 31) | 0x80000000u;   // flip: total order
    return (u & ~63u) | (unsigned int)idx;
}

__global__ __launch_bounds__(THREADS)
void loss_kernel(const float* __restrict__ scores,
                 const float* __restrict__ labels,
                 float* __restrict__ out) {
    __shared__ float wpart[WARPS];
    __shared__ bool  isLast;

    const int warp = threadIdx.x >> 5;
    const int lane = threadIdx.x & 31;
    const int wg   = blockIdx.x * WARPS + warp;

    const float c0 = 63.0f - 4.0f * (float)lane;   // weight (63-2p) at p=2*lane
    const float c1 = c0 - 2.0f;                    // at p=2*lane+1

    unsigned int key[RPW][2];
    float        v[RPW][2];
    float        t[RPW][2];

#pragma unroll
    for (int r = 0; r < RPW; ++r) {
        const int row = wg * RPW + r;
        const float2 L = reinterpret_cast<const float2*>(labels)[row * 32 + lane];
        const float2 S = reinterpret_cast<const float2*>(scores)[row * 32 + lane];
        v[r][0] = S.x;  v[r][1] = S.y;
        key[r][0] = pack_key(L.x, 2 * lane);
        key[r][1] = pack_key(L.y, 2 * lane + 1);
    }

    // ---- bitonic sort of 64 uint keys (idx = 2*lane + slot), 2 rows interleaved ----
#pragma unroll
    for (int k = 2; k <= 64; k <<= 1) {
        const bool up = (lane & (k >> 1)) == 0;
#pragma unroll
        for (int d = k >> 1; d >= 2; d >>= 1) {
            const bool wantMin = (((lane & (d >> 1)) == 0) == up);
#pragma unroll
            for (int r = 0; r < RPW; ++r) {
                const unsigned int p0 = __shfl_xor_sync(0xffffffffu, key[r][0], d >> 1);
                const unsigned int p1 = __shfl_xor_sync(0xffffffffu, key[r][1], d >> 1);
                key[r][0] = wantMin ? umin(key[r][0], p0) : umax(key[r][0], p0);
                key[r][1] = wantMin ? umin(key[r][1], p1) : umax(key[r][1], p1);
            }
        }
#pragma unroll
        for (int r = 0; r < RPW; ++r) {
            const unsigned int lo = umin(key[r][0], key[r][1]);
            const unsigned int hi = umax(key[r][0], key[r][1]);
            key[r][0] = up ? lo : hi;
            key[r][1] = up ? hi : lo;
        }
    }

    float acc = 0.f;

    // ---- gather scores at sorted order, build t, accumulate linear term ----
#pragma unroll
    for (int r = 0; r < RPW; ++r) {
        const int i0 = (int)(key[r][0] & 63u);
        const int i1 = (int)(key[r][1] & 63u);
        const float a0 = __shfl_sync(0xffffffffu, v[r][0], i0 >> 1);
        const float b0 = __shfl_sync(0xffffffffu, v[r][1], i0 >> 1);
        const float a1 = __shfl_sync(0xffffffffu, v[r][0], i1 >> 1);
        const float b1 = __shfl_sync(0xffffffffu, v[r][1], i1 >> 1);
        const float g0 = (i0 & 1) ? b0 : a0;
        const float g1 = (i1 & 1) ? b1 : a1;
        t[r][0] = fmaf(-0.2f, (float)lane, g0);           // - 0.1 * (2*lane)
        t[r][1] = fmaf(-0.2f, (float)lane, g1) - 0.1f;    // - 0.1 * (2*lane+1)
        acc += t[r][0] * c0 + t[r][1] * c1;
    }

    // ---- keys-only bitonic sort of t (ascending), 2 rows interleaved ----
#pragma unroll
    for (int k = 2; k <= 64; k <<= 1) {
        const bool up = (lane & (k >> 1)) == 0;
#pragma unroll
        for (int d = k >> 1; d >= 2; d >>= 1) {
            const bool wantMin = (((lane & (d >> 1)) == 0) == up);
#pragma unroll
            for (int r = 0; r < RPW; ++r) {
                const float p0 = __shfl_xor_sync(0xffffffffu, t[r][0], d >> 1);
                const float p1 = __shfl_xor_sync(0xffffffffu, t[r][1], d >> 1);
                t[r][0] = wantMin ? fminf(t[r][0], p0) : fmaxf(t[r][0], p0);
                t[r][1] = wantMin ? fminf(t[r][1], p1) : fmaxf(t[r][1], p1);
            }
        }
#pragma unroll
        for (int r = 0; r < RPW; ++r) {
            const float lo = fminf(t[r][0], t[r][1]);
            const float hi = fmaxf(t[r][0], t[r][1]);
            t[r][0] = up ? lo : hi;
            t[r][1] = up ? hi : lo;
        }
    }

    // abs term: sum_m v_m*(2m-63) = -(sum at weights (63-2m))
#pragma unroll
    for (int r = 0; r < RPW; ++r)
        acc -= t[r][0] * c0 + t[r][1] * c1;

    // ---- deterministic block reduction ----
    const float ws = warp_sum(acc);
    if (lane == 0) wpart[warp] = ws;
    __syncthreads();
    if (warp == 0) {
        float x = (lane < WARPS) ? wpart[lane] : 0.f;
        x = warp_sum(x);
        if (lane == 0) {
            g_partials[blockIdx.x] = x;
            __threadfence();
            isLast = (atomicAdd(&g_done, 1u) == GRID - 1);
        }
    }
    __syncthreads();

    // ---- last block: fixed-order final reduction, reset counter ----
    if (isLast) {
        float x = 0.f;
#pragma unroll
        for (int i = 0; i < GRID / THREADS; ++i)
            x += __ldcg(&g_partials[threadIdx.x + i * THREADS]);
        x = warp_sum(x);
        if (lane == 0) wpart[warp] = x;
        __syncthreads();
        if (warp == 0) {
            float y = (lane < WARPS) ? wpart[lane] : 0.f;
            y = warp_sum(y);
            if (lane == 0) {
                out[0] = y * (0.5f / (float)BATCH);
                g_done = 0;
            }
        }
    }
}

extern "C" void kernel_launch(void* const* d_in, const int* in_sizes, int n_in,
                              void* d_out, int out_size) {
    const float* scores = (const float*)d_in[0];
    const float* labels = (const float*)d_in[1];
    float* out = (float*)d_out;
    loss_kernel<<<GRID, THREADS>>>(scores, labels, out);
}

// round 4
// speedup vs baseline: 2.0616x; 1.1940x over previous
#include <cuda_runtime.h>
#include <cuda_bf16.h>

// loss = (1/B) * sum_b sum_{i<j} max(0, (s_i - s_j) + 0.1*(j-i)),  s = scores[argsort(labels)]
// t_k = s_sorted_k - 0.1k  ->  pair term = relu(t_i - t_j), and
//   sum_{i<j} relu(t_i-t_j) = 0.5*[ sum_k t_k*(63-2k) + sum_m v_m*(2m-63) ],  v = sort(t) asc.
//
// Layout: 4 elements per lane, 16 lanes per row; each warp sorts TWO rows at once
// (lanes 0-15 row A, 16-31 row B; all shfl distances < 16 stay in the half-warp).
// Bitonic-64 then needs only 10 inter-lane shuffle steps; d=2/d=1 steps are
// intra-lane register compare-exchanges on the ALU pipe.
// Sort #1: labels as order-preserving uint32 keys with embedded 6-bit index (stable).
// Score gather after sort #1 goes through a small smem staging buffer (LDS, not SHFL).
// Sort #2: keys-only float sort of t.

#define BATCH 32768
#define THREADS 256
#define WARPS 8
#define GRID (BATCH / (WARPS * 2))   // 2048 blocks, 2 rows per warp

__device__ float g_partials[GRID];
__device__ unsigned int g_done = 0;

__device__ __forceinline__ float warp_sum(float v) {
#pragma unroll
    for (int o = 16; o; o >>= 1) v += __shfl_xor_sync(0xffffffffu, v, o);
    return v;
}

// ---- generic min/max ----
__device__ __forceinline__ float        tmin(float a, float b)               { return fminf(a, b); }
__device__ __forceinline__ float        tmax(float a, float b)               { return fmaxf(a, b); }
__device__ __forceinline__ unsigned int tmin(unsigned int a, unsigned int b) { return umin(a, b); }
__device__ __forceinline__ unsigned int tmax(unsigned int a, unsigned int b) { return umax(a, b); }

// inter-lane step: partner = lane ^ ld (element distance 4*ld), keep min iff wm
template <class T>
__device__ __forceinline__ void inter(T v[4], int ld, bool wm) {
#pragma unroll
    for (int s = 0; s < 4; ++s) {
        const T p = __shfl_xor_sync(0xffffffffu, v[s], ld);
        v[s] = wm ? tmin(v[s], p) : tmax(v[s], p);
    }
}

// intra-lane d=2: CE(0,2), CE(1,3); lower side keeps min iff U
template <class T>
__device__ __forceinline__ void ce_d2(T v[4], bool U) {
    const T a0 = v[0], a2 = v[2], a1 = v[1], a3 = v[3];
    v[0] = U ? tmin(a0, a2) : tmax(a0, a2);
    v[2] = U ? tmax(a0, a2) : tmin(a0, a2);
    v[1] = U ? tmin(a1, a3) : tmax(a1, a3);
    v[3] = U ? tmax(a1, a3) : tmin(a1, a3);
}

// intra-lane d=1: CE(0,1), CE(2,3)
template <class T>
__device__ __forceinline__ void ce_d1(T v[4], bool U) {
    const T a0 = v[0], a1 = v[1], a2 = v[2], a3 = v[3];
    v[0] = U ? tmin(a0, a1) : tmax(a0, a1);
    v[1] = U ? tmax(a0, a1) : tmin(a0, a1);
    v[2] = U ? tmin(a2, a3) : tmax(a2, a3);
    v[3] = U ? tmax(a2, a3) : tmin(a2, a3);
}

// ascending bitonic sort of 64 elements: idx = 4*lg + slot, lg = lane & 15
template <class T>
__device__ __forceinline__ void bitonic64(T v[4], int lg) {
    // k = 2 (compile-time directions)
    { const T a = tmin(v[0], v[1]), b = tmax(v[0], v[1]); v[0] = a; v[1] = b;
      const T c = tmax(v[2], v[3]), d = tmin(v[2], v[3]); v[2] = c; v[3] = d; }
    // k = 4
    { const bool U = (lg & 1) == 0; ce_d2(v, U); ce_d1(v, U); }
    // k = 8
    { const bool U = (lg & 2) == 0;
      inter(v, 1, ((lg & 1) == 0) == U);
      ce_d2(v, U); ce_d1(v, U); }
    // k = 16
    { const bool U = (lg & 4) == 0;
      inter(v, 2, ((lg & 2) == 0) == U);
      inter(v, 1, ((lg & 1) == 0) == U);
      ce_d2(v, U); ce_d1(v, U); }
    // k = 32
    { const bool U = (lg & 8) == 0;
      inter(v, 4, ((lg & 4) == 0) == U);
      inter(v, 2, ((lg & 2) == 0) == U);
      inter(v, 1, ((lg & 1) == 0) == U);
      ce_d2(v, U); ce_d1(v, U); }
    // k = 64 (up for every idx; final merge ascending)
    { inter(v, 8, (lg & 8) == 0);
      inter(v, 4, (lg & 4) == 0);
      inter(v, 2, (lg & 2) == 0);
      inter(v, 1, (lg & 1) == 0);
      ce_d2(v, true); ce_d1(v, true); }
}

// order-preserving float -> uint32 (ascending), low 6 bits carry original index
__device__ __forceinline__ unsigned int pack_key(float f, int idx) {
    unsigned int u = __float_as_uint(f);
    u ^= (unsigned int)((int)u >> 31) | 0x80000000u;
    return (u & ~63u) | (unsigned int)idx;
}

__global__ __launch_bounds__(THREADS)
void loss_kernel(const float* __restrict__ scores,
                 const float* __restrict__ labels,
                 float* __restrict__ out) {
    __shared__ float shsc[WARPS][2 * 72];   // per-warp score staging (2 rows, 72-float stride)
    __shared__ float wpart[WARPS];
    __shared__ bool  isLast;

    const int warp = threadIdx.x >> 5;
    const int lane = threadIdx.x & 31;
    const int lg   = lane & 15;          // row-local lane
    const int half = lane >> 4;          // 0 = row A, 1 = row B
    const int wg   = blockIdx.x * WARPS + warp;
    const int row  = wg * 2 + half;

    // coalesced float4 loads: lane owns elements 4lg .. 4lg+3 of its row
    const float4 L = reinterpret_cast<const float4*>(labels)[row * 16 + lg];
    const float4 S = reinterpret_cast<const float4*>(scores)[row * 16 + lg];

    // stage scores in smem for the post-sort gather
    *reinterpret_cast<float4*>(&shsc[warp][half * 72 + 4 * lg]) = S;
    __syncwarp();

    unsigned int key[4];
    key[0] = pack_key(L.x, 4 * lg + 0);
    key[1] = pack_key(L.y, 4 * lg + 1);
    key[2] = pack_key(L.z, 4 * lg + 2);
    key[3] = pack_key(L.w, 4 * lg + 3);

    bitonic64(key, lg);                  // sort #1: by label (stable via embedded index)

    // gather scores at sorted order, build t_p = s_sorted_p - 0.1*p
    const float lgf = (float)lg;
    float t[4];
#pragma unroll
    for (int s = 0; s < 4; ++s) {
        const float sv = shsc[warp][half * 72 + (int)(key[s] & 63u)];
        t[s] = fmaf(-0.4f, lgf, sv) - 0.1f * (float)s;
    }

    // coefficients c_p = 63 - 2p at p = 4lg + s
    const float cb = 63.0f - 8.0f * lgf;
    float acc = t[0] * cb + t[1] * (cb - 2.0f) + t[2] * (cb - 4.0f) + t[3] * (cb - 6.0f);

    bitonic64(t, lg);                    // sort #2: values only

    // abs term: sum_m v_m*(2m-63) = -(weighted sum at (63-2m))
    acc -= t[0] * cb + t[1] * (cb - 2.0f) + t[2] * (cb - 4.0f) + t[3] * (cb - 6.0f);

    // ---- deterministic block reduction (covers both rows: lanes 0-15 A, 16-31 B) ----
    const float ws = warp_sum(acc);
    if (lane == 0) wpart[warp] = ws;
    __syncthreads();
    if (warp == 0) {
        float x = (lane < WARPS) ? wpart[lane] : 0.f;
        x = warp_sum(x);
        if (lane == 0) {
            g_partials[blockIdx.x] = x;
            __threadfence();
            isLast = (atomicAdd(&g_done, 1u) == GRID - 1);
        }
    }
    __syncthreads();

    // ---- last block: fixed-order final reduction, reset counter ----
    if (isLast) {
        float x = 0.f;
#pragma unroll
        for (int i = 0; i < GRID / THREADS; ++i)
            x += __ldcg(&g_partials[threadIdx.x + i * THREADS]);
        x = warp_sum(x);
        if (lane == 0) wpart[warp] = x;
        __syncthreads();
        if (warp == 0) {
            float y = (lane < WARPS) ? wpart[lane] : 0.f;
            y = warp_sum(y);
            if (lane == 0) {
                out[0] = y * (0.5f / (float)BATCH);
                g_done = 0;
            }
        }
    }
}

extern "C" void kernel_launch(void* const* d_in, const int* in_sizes, int n_in,
                              void* d_out, int out_size) {
    const float* scores = (const float*)d_in[0];
    const float* labels = (const float*)d_in[1];
    float* out = (float*)d_out;
    loss_kernel<<<GRID, THREADS>>>(scores, labels, out);
}

// round 5
// speedup vs baseline: 2.3866x; 1.1577x over previous
#include <cuda_runtime.h>
#include <cuda_bf16.h>

// loss = (1/B) * sum_b sum_{i<j} max(0, (s_i - s_j) + 0.1*(j-i)),  s = scores[argsort(labels)]
// t_k = s_sorted_k - 0.1k  ->  pair term = relu(t_i - t_j) = ((t_i-t_j)+|t_i-t_j|)/2, so
//   sum_{i<j} relu(t_i-t_j) = 0.5*[ sum_k t_k*(63-2k) + sum_m v_m*(2m-63) ],  v = sort(t) asc.
//
// Layout: 8 elements/lane, 8 lanes/row, FOUR rows per warp (lane = quarter*8 + lg).
// Bitonic-64 needs only 6 inter-lane shuffle steps; k=2,k=4 phases are fully
// compile-time (pure min/max); runtime-direction CEs use conditional-swap (SETP+2SEL).
// Sort #1: labels as order-preserving uint32 keys with embedded 6-bit index (stable
// argsort). Score gather via smem staging. Sort #2: keys-only float sort of t.

#define BATCH 32768
#define THREADS 256
#define WARPS 8
#define GRID (BATCH / (WARPS * 4))   // 1024 blocks, 4 rows per warp

__device__ float g_partials[GRID];
__device__ unsigned int g_done = 0;

__device__ __forceinline__ float warp_sum(float v) {
#pragma unroll
    for (int o = 16; o; o >>= 1) v += __shfl_xor_sync(0xffffffffu, v, o);
    return v;
}

__device__ __forceinline__ float        tmin(float a, float b)               { return fminf(a, b); }
__device__ __forceinline__ float        tmax(float a, float b)               { return fmaxf(a, b); }
__device__ __forceinline__ unsigned int tmin(unsigned int a, unsigned int b) { return umin(a, b); }
__device__ __forceinline__ unsigned int tmax(unsigned int a, unsigned int b) { return umax(a, b); }

// compile-time direction CEs (2 inst each)
template <class T> __device__ __forceinline__ void ceAsc (T& a, T& b) { const T lo = tmin(a, b); b = tmax(a, b); a = lo; }
template <class T> __device__ __forceinline__ void ceDesc(T& a, T& b) { const T hi = tmax(a, b); b = tmin(a, b); a = hi; }

// runtime-direction CE: conditional swap (SETP + 2 SEL)
template <class T>
__device__ __forceinline__ void ceSwap(T& a, T& b, bool up) {
    const bool sw = ((b < a) == up);      // up: swap if a>b; down: swap if b>=a (ties harmless)
    const T x = a, y = b;
    a = sw ? y : x;
    b = sw ? x : y;
}

// inter-lane step at lane distance ld: keep min iff wm (SHFL + SETP + SEL per reg)
template <class T>
__device__ __forceinline__ void interCE(T v[8], int ld, bool wm) {
#pragma unroll
    for (int s = 0; s < 8; ++s) {
        const T p = __shfl_xor_sync(0xffffffffu, v[s], ld);
        v[s] = ((p < v[s]) == wm) ? p : v[s];
    }
}

// intra-lane merge of a bitonic 8-seq, runtime direction
template <class T>
__device__ __forceinline__ void intra3(T v[8], bool up) {
    ceSwap(v[0], v[4], up); ceSwap(v[1], v[5], up); ceSwap(v[2], v[6], up); ceSwap(v[3], v[7], up);
    ceSwap(v[0], v[2], up); ceSwap(v[1], v[3], up); ceSwap(v[4], v[6], up); ceSwap(v[5], v[7], up);
    ceSwap(v[0], v[1], up); ceSwap(v[2], v[3], up); ceSwap(v[4], v[5], up); ceSwap(v[6], v[7], up);
}

// intra-lane merge, ascending (compile-time, pure min/max)
template <class T>
__device__ __forceinline__ void intra3Asc(T v[8]) {
    ceAsc(v[0], v[4]); ceAsc(v[1], v[5]); ceAsc(v[2], v[6]); ceAsc(v[3], v[7]);
    ceAsc(v[0], v[2]); ceAsc(v[1], v[3]); ceAsc(v[4], v[6]); ceAsc(v[5], v[7]);
    ceAsc(v[0], v[1]); ceAsc(v[2], v[3]); ceAsc(v[4], v[5]); ceAsc(v[6], v[7]);
}

// ascending bitonic sort of 64 elements: idx = 8*lg + slot, lg = lane & 7
template <class T>
__device__ __forceinline__ void bitonic64(T v[8], int lg) {
    // k=2: dir = (idx&2)==0 -> slot-indexed, compile-time
    ceAsc (v[0], v[1]); ceDesc(v[2], v[3]); ceAsc (v[4], v[5]); ceDesc(v[6], v[7]);
    // k=4: dir = (idx&4)==0 -> compile-time; layers d=2, d=1
    ceAsc (v[0], v[2]); ceAsc (v[1], v[3]); ceDesc(v[4], v[6]); ceDesc(v[5], v[7]);
    ceAsc (v[0], v[1]); ceAsc (v[2], v[3]); ceDesc(v[4], v[5]); ceDesc(v[6], v[7]);
    // k=8: dir = (lg&1)==0, fully intra-lane
    { const bool up = (lg & 1) == 0; intra3(v, up); }
    // k=16
    { const bool up = (lg & 2) == 0;
      interCE(v, 1, ((lg & 1) == 0) == up);
      intra3(v, up); }
    // k=32
    { const bool up = (lg & 4) == 0;
      interCE(v, 2, ((lg & 2) == 0) == up);
      interCE(v, 1, ((lg & 1) == 0) == up);
      intra3(v, up); }
    // k=64: ascending everywhere
    { interCE(v, 4, (lg & 4) == 0);
      interCE(v, 2, (lg & 2) == 0);
      interCE(v, 1, (lg & 1) == 0);
      intra3Asc(v); }
}

// order-preserving float -> uint32 (ascending), low 6 bits carry original index
__device__ __forceinline__ unsigned int pack_key(float f, int idx) {
    unsigned int u = __float_as_uint(f);
    u ^= (unsigned int)((int)u >> 31) | 0x80000000u;
    return (u & ~63u) | (unsigned int)idx;
}

__global__ __launch_bounds__(THREADS)
void loss_kernel(const float* __restrict__ scores,
                 const float* __restrict__ labels,
                 float* __restrict__ out) {
    __shared__ float shsc[WARPS][4 * 72];   // per-warp score staging: 4 rows, stride 72
    __shared__ float wpart[WARPS];
    __shared__ bool  isLast;

    const int warp = threadIdx.x >> 5;
    const int lane = threadIdx.x & 31;
    const int lg   = lane & 7;            // row-local lane (8 per row)
    const int qtr  = lane >> 3;           // which of the 4 rows this warp handles
    const int wg   = blockIdx.x * WARPS + warp;
    const int row  = wg * 4 + qtr;

    // lane owns elements 8lg..8lg+7 of its row (two float4 loads, coalesced)
    const float4 L0 = reinterpret_cast<const float4*>(labels)[row * 16 + 2 * lg];
    const float4 L1 = reinterpret_cast<const float4*>(labels)[row * 16 + 2 * lg + 1];
    const float4 S0 = reinterpret_cast<const float4*>(scores)[row * 16 + 2 * lg];
    const float4 S1 = reinterpret_cast<const float4*>(scores)[row * 16 + 2 * lg + 1];

    // stage scores for post-sort gather
    *reinterpret_cast<float4*>(&shsc[warp][qtr * 72 + 8 * lg])     = S0;
    *reinterpret_cast<float4*>(&shsc[warp][qtr * 72 + 8 * lg + 4]) = S1;
    __syncwarp();

    unsigned int key[8];
    key[0] = pack_key(L0.x, 8 * lg + 0);
    key[1] = pack_key(L0.y, 8 * lg + 1);
    key[2] = pack_key(L0.z, 8 * lg + 2);
    key[3] = pack_key(L0.w, 8 * lg + 3);
    key[4] = pack_key(L1.x, 8 * lg + 4);
    key[5] = pack_key(L1.y, 8 * lg + 5);
    key[6] = pack_key(L1.z, 8 * lg + 6);
    key[7] = pack_key(L1.w, 8 * lg + 7);

    bitonic64(key, lg);                   // sort #1: by label (stable via embedded index)

    // gather scores at sorted order; t_p = s_sorted_p - 0.1p, p = 8lg + s
    const float lgf = (float)lg;
    float t[8];
#pragma unroll
    for (int s = 0; s < 8; ++s) {
        const float sv = shsc[warp][qtr * 72 + (int)(key[s] & 63u)];
        t[s] = fmaf(-0.8f, lgf, sv) - 0.1f * (float)s;
    }

    // linear term: c_p = 63 - 2p = (63 - 16lg) - 2s
    const float cb = 63.0f - 16.0f * lgf;
    float acc = 0.f;
#pragma unroll
    for (int s = 0; s < 8; ++s) acc = fmaf(t[s], cb - 2.0f * (float)s, acc);

    bitonic64(t, lg);                     // sort #2: values only

    // abs term: sum_m v_m*(2m-63) = -(weighted sum at (63-2m))
    float acc2 = 0.f;
#pragma unroll
    for (int s = 0; s < 8; ++s) acc2 = fmaf(t[s], cb - 2.0f * (float)s, acc2);
    acc -= acc2;

    // ---- deterministic block reduction (lanes cover 4 rows) ----
    const float ws = warp_sum(acc);
    if (lane == 0) wpart[warp] = ws;
    __syncthreads();
    if (warp == 0) {
        float x = (lane < WARPS) ? wpart[lane] : 0.f;
        x = warp_sum(x);
        if (lane == 0) {
            g_partials[blockIdx.x] = x;
            __threadfence();
            isLast = (atomicAdd(&g_done, 1u) == GRID - 1);
        }
    }
    __syncthreads();

    // ---- last block: fixed-order final reduction, reset counter ----
    if (isLast) {
        float x = 0.f;
#pragma unroll
        for (int i = 0; i < GRID / THREADS; ++i)
            x += __ldcg(&g_partials[threadIdx.x + i * THREADS]);
        x = warp_sum(x);
        if (lane == 0) wpart[warp] = x;
        __syncthreads();
        if (warp == 0) {
            float y = (lane < WARPS) ? wpart[lane] : 0.f;
            y = warp_sum(y);
            if (lane == 0) {
                out[0] = y * (0.5f / (float)BATCH);
                g_done = 0;
            }
        }
    }
}

extern "C" void kernel_launch(void* const* d_in, const int* in_sizes, int n_in,
                              void* d_out, int out_size) {
    const float* scores = (const float*)d_in[0];
    const float* labels = (const float*)d_in[1];
    float* out = (float*)d_out;
    loss_kernel<<<GRID, THREADS>>>(scores, labels, out);
}